// round 12
// baseline (speedup 1.0000x reference)
#include <cuda_runtime.h>
#include <cuda_fp16.h>
#include <cstdint>

#define S_LEN 2048
#define NQT 16
#define NBH 32
#define NELEM (NBH * S_LEN * 64)
#define QSCALE 0.18033688011112042f   // (1/8) * log2(e)

#define LQ 72
#define LK 72
#define LV 72
// 3 K/V stages of 9216 halves each; Q staged into buffer 2 (reused as stage 2)
#define H_KB(b) ((b) * 9216)
#define H_VB(b) ((b) * 9216 + 4608)
#define H_QS 18432
#define SMEM_BYTES (27648 * 2)   // 55296 B -> 2 CTAs/SM

__device__ __half g_kh[NELEM];
__device__ __half g_vh[NELEM];

__device__ __forceinline__ uint32_t smem_u32(const void* p) {
    uint32_t a;
    asm("{ .reg .u64 t; cvta.to.shared.u64 t, %1; cvt.u32.u64 %0, t; }" : "=r"(a) : "l"(p));
    return a;
}
__device__ __forceinline__ uint32_t ex2_h2(uint32_t x) {
    uint32_t y; asm("ex2.approx.f16x2 %0, %1;" : "=r"(y) : "r"(x)); return y;
}
__device__ __forceinline__ void cpa16(uint32_t s, const void* g) {
    asm volatile("cp.async.cg.shared.global [%0], [%1], 16;" :: "r"(s), "l"(g));
}
#define CP_COMMIT() asm volatile("cp.async.commit_group;" ::: "memory")
#define CP_WAIT0()  asm volatile("cp.async.wait_group 0;" ::: "memory")
#define CP_WAIT1()  asm volatile("cp.async.wait_group 1;" ::: "memory")

__device__ __forceinline__ void ldsm4(uint32_t& r0, uint32_t& r1, uint32_t& r2,
                                      uint32_t& r3, uint32_t a) {
    asm volatile("ldmatrix.sync.aligned.m8n8.x4.shared.b16 {%0,%1,%2,%3}, [%4];"
                 : "=r"(r0), "=r"(r1), "=r"(r2), "=r"(r3) : "r"(a));
}
__device__ __forceinline__ void ldsm4t(uint32_t& r0, uint32_t& r1, uint32_t& r2,
                                       uint32_t& r3, uint32_t a) {
    asm volatile("ldmatrix.sync.aligned.m8n8.x4.trans.shared.b16 {%0,%1,%2,%3}, [%4];"
                 : "=r"(r0), "=r"(r1), "=r"(r2), "=r"(r3) : "r"(a));
}
__device__ __forceinline__ void ldsm2t(uint32_t& r0, uint32_t& r1, uint32_t a) {
    asm volatile("ldmatrix.sync.aligned.m8n8.x2.trans.shared.b16 {%0,%1}, [%2];"
                 : "=r"(r0), "=r"(r1) : "r"(a));
}
__device__ __forceinline__ void mma16(float d[4], const uint32_t a[4],
                                      uint32_t b0, uint32_t b1) {
    asm volatile(
        "mma.sync.aligned.m16n8k16.row.col.f32.f16.f16.f32 "
        "{%0,%1,%2,%3}, {%4,%5,%6,%7}, {%8,%9}, {%0,%1,%2,%3};"
        : "+f"(d[0]), "+f"(d[1]), "+f"(d[2]), "+f"(d[3])
        : "r"(a[0]), "r"(a[1]), "r"(a[2]), "r"(a[3]), "r"(b0), "r"(b1));
}

// ---- pre-pass: K/V f32 -> f16 ----
__global__ __launch_bounds__(256)
void cvt_f16(const float* __restrict__ k, const float* __restrict__ v) {
    size_t i = ((size_t)blockIdx.x * 256 + threadIdx.x) * 4;
    float4 b = *(const float4*)(k + i);
    *(__half2*)(g_kh + i)     = __floats2half2_rn(b.x, b.y);
    *(__half2*)(g_kh + i + 2) = __floats2half2_rn(b.z, b.w);
    float4 c = *(const float4*)(v + i);
    *(__half2*)(g_vh + i)     = __floats2half2_rn(c.x, c.y);
    *(__half2*)(g_vh + i + 2) = __floats2half2_rn(c.z, c.w);
}

// K+V tile (64x64 halves each) into stage b, 256 threads
__device__ __forceinline__ void cp_tile(uint32_t su, int b,
                                        const __half* kp, const __half* vp, int tid) {
    #pragma unroll
    for (int i = 0; i < 2; i++) {
        int c = i * 256 + tid;
        int row = c >> 3, seg = c & 7;
        cpa16(su + (H_KB(b) + row * LK + seg * 8) * 2, kp + row * 64 + seg * 8);
    }
    #pragma unroll
    for (int i = 0; i < 2; i++) {
        int c = i * 256 + tid;
        int row = c >> 3, seg = c & 7;
        cpa16(su + (H_VB(b) + row * LV + seg * 8) * 2, vp + row * 64 + seg * 8);
    }
}

__global__ __launch_bounds__(256, 2)
void fa_f16(const float* __restrict__ qf, float* __restrict__ out) {
    extern __shared__ char smc[];
    const uint32_t su = smem_u32(smc);
    const int tid = threadIdx.x;
    const int w8 = tid >> 5, lane = tid & 31;
    const int lq = lane >> 2, lr = lane & 3;
    const int g8 = lane >> 3, lr8 = lane & 7;

    const int qt = NQT - 1 - (int)blockIdx.x;   // big tiles first
    const int bh = blockIdx.y;
    const int T  = 2 * qt + 2;

    const float* qb = qf + ((size_t)bh * S_LEN + (size_t)qt * 128) * 64;
    const __half* kh = g_kh + (size_t)bh * S_LEN * 64;
    const __half* vh = g_vh + (size_t)bh * S_LEN * 64;

    // prologue: start cp for tiles 0,1 immediately
    cp_tile(su, 0, kh, vh, tid);
    CP_COMMIT();
    if (T >= 2) { cp_tile(su, 1, kh + 4096, vh + 4096, tid); }
    CP_COMMIT();

    // ones columns (col 64 = 1.0, 65-71 = 0) in all 3 V stages
    if (tid < 192) {
        int b = tid >> 6, row = tid & 63;
        *(uint4*)(smc + (H_VB(b) + row * LV + 64) * 2) = make_uint4(0x00003C00u, 0, 0, 0);
    }
    // Q: f32 LDG -> scaled f16 -> STS into buffer 2 (cols 0-63 only)
    #pragma unroll
    for (int i = 0; i < 8; i++) {
        int c = i * 256 + tid;                  // 2048 float4(f32) slots
        int row = c >> 4, seg = c & 15;
        float4 t = *(const float4*)(qb + row * 64 + seg * 4);
        __half2 h0 = __floats2half2_rn(t.x * QSCALE, t.y * QSCALE);
        __half2 h1 = __floats2half2_rn(t.z * QSCALE, t.w * QSCALE);
        uint2 hh = make_uint2(*(uint32_t*)&h0, *(uint32_t*)&h1);
        *(uint2*)(smc + (H_QS + row * LQ + seg * 4) * 2) = hh;
    }
    __syncthreads();                            // Q visible

    // hoist Q fragments (invariant): 16 regs; buffer 2 then becomes stage 2
    uint32_t qa[4][4];
    #pragma unroll
    for (int ks = 0; ks < 4; ks++) {
        int row = w8 * 16 + (g8 & 1) * 8 + lr8;
        int hc  = ks * 16 + (g8 >> 1) * 8;
        ldsm4(qa[ks][0], qa[ks][1], qa[ks][2], qa[ks][3],
              su + (H_QS + row * LQ + hc) * 2);
    }
    CP_WAIT1();                                 // tile 0 landed
    __syncthreads();                            // qa hoisted by all; stage0 visible

    float o[9][4];
    #pragma unroll
    for (int n = 0; n < 9; n++)
        #pragma unroll
        for (int e = 0; e < 4; e++) o[n][e] = 0.0f;

    const int rg0 = qt * 128 + w8 * 16 + lq;
    int bs = 0;                                 // current stage

    for (int it = 0; it < T; it++) {
        const uint32_t koh = H_KB(bs), voh = H_VB(bs);
        const bool need_mask = (it >= 2 * qt);  // diagonal spans last TWO tiles

        // ---- S = Q @ K^T fused with softmax (np-outer) ----
        uint32_t pa[4][4];
        #pragma unroll
        for (int np = 0; np < 4; np++) {
            float s0[4] = {0.f, 0.f, 0.f, 0.f};
            float s1[4] = {0.f, 0.f, 0.f, 0.f};
            #pragma unroll
            for (int ks = 0; ks < 4; ks++) {
                uint32_t b0, b1, b2, b3;
                int row = (2 * np + (g8 >> 1)) * 8 + lr8;
                int hc  = ks * 16 + (g8 & 1) * 8;
                ldsm4(b0, b1, b2, b3, su + (koh + row * LK + hc) * 2);
                mma16(s0, qa[ks], b0, b1);
                mma16(s1, qa[ks], b2, b3);
            }
            if (need_mask) {
                const int jg0 = it * 64 + (2 * np) * 8 + 2 * lr;
                if (jg0     > rg0    ) s0[0] = -1e30f;
                if (jg0 + 1 > rg0    ) s0[1] = -1e30f;
                if (jg0     > rg0 + 8) s0[2] = -1e30f;
                if (jg0 + 1 > rg0 + 8) s0[3] = -1e30f;
                const int jg1 = jg0 + 8;
                if (jg1     > rg0    ) s1[0] = -1e30f;
                if (jg1 + 1 > rg0    ) s1[1] = -1e30f;
                if (jg1     > rg0 + 8) s1[2] = -1e30f;
                if (jg1 + 1 > rg0 + 8) s1[3] = -1e30f;
            }
            __half2 a01 = __floats2half2_rn(s0[0], s0[1]);   // masked -> -inf
            __half2 a23 = __floats2half2_rn(s0[2], s0[3]);
            __half2 b01 = __floats2half2_rn(s1[0], s1[1]);
            __half2 b23 = __floats2half2_rn(s1[2], s1[3]);
            pa[np][0] = ex2_h2(*(uint32_t*)&a01);            // ex2(-inf) = 0
            pa[np][1] = ex2_h2(*(uint32_t*)&a23);
            pa[np][2] = ex2_h2(*(uint32_t*)&b01);
            pa[np][3] = ex2_h2(*(uint32_t*)&b23);
        }

        // ---- O += P @ V  (ones column -> lsum in o[8]) ----
        #pragma unroll
        for (int ks = 0; ks < 4; ks++) {
            int row = ks * 16 + (g8 & 1) * 8 + lr8;
            #pragma unroll
            for (int np = 0; np < 4; np++) {
                uint32_t b0, b1, b2, b3;
                int hc = (2 * np + (g8 >> 1)) * 8;
                ldsm4t(b0, b1, b2, b3, su + (voh + row * LV + hc) * 2);
                mma16(o[2 * np],     pa[ks], b0, b1);
                mma16(o[2 * np + 1], pa[ks], b2, b3);
            }
            uint32_t w0, w1;
            ldsm2t(w0, w1, su + (voh + row * LV + 64) * 2);
            mma16(o[8], pa[ks], w0, w1);
        }

        // ---- 3-stage ring: one prefetch + one wait + ONE sync per tile ----
        if (it + 2 < T) {
            int pf = bs - 1; if (pf < 0) pf = 2;   // (bs+2)%3
            cp_tile(su, pf, kh + (size_t)(it + 2) * 4096,
                            vh + (size_t)(it + 2) * 4096, tid);
            CP_COMMIT();
            CP_WAIT1();        // tile it+1 landed
        } else {
            CP_WAIT0();
        }
        __syncthreads();       // everyone done with stage bs; next stage visible
        bs = (bs == 2) ? 0 : bs + 1;
    }

    // ---- epilogue: lsum from ones column, normalize, store ----
    float l0 = __shfl_sync(0xffffffffu, o[8][0], lane & ~3);
    float l1 = __shfl_sync(0xffffffffu, o[8][2], lane & ~3);
    const float inv0 = __fdividef(1.0f, l0);
    const float inv1 = __fdividef(1.0f, l1);
    float* ob = out + ((size_t)bh * S_LEN + rg0) * 64;
    #pragma unroll
    for (int n = 0; n < 8; n++) {
        const int col = n * 8 + 2 * lr;
        *(float2*)(ob + col) = make_float2(o[n][0] * inv0, o[n][1] * inv0);
        *(float2*)(ob + 8 * 64 + col) = make_float2(o[n][2] * inv1, o[n][3] * inv1);
    }
}

extern "C" void kernel_launch(void* const* d_in, const int* in_sizes, int n_in,
                              void* d_out, int out_size) {
    (void)in_sizes; (void)n_in; (void)out_size;
    cvt_f16<<<NELEM / (256 * 4), 256>>>((const float*)d_in[1], (const float*)d_in[2]);
    cudaFuncSetAttribute(fa_f16, cudaFuncAttributeMaxDynamicSharedMemorySize, SMEM_BYTES);
    dim3 grid(NQT, NBH);
    fa_f16<<<grid, 256, SMEM_BYTES>>>((const float*)d_in[0], (float*)d_out);
}

// round 13
// speedup vs baseline: 1.3692x; 1.3692x over previous
#include <cuda_runtime.h>
#include <cuda_fp16.h>
#include <cstdint>

#define S_LEN 2048
#define NQT 16
#define NBH 32
#define NELEM (NBH * S_LEN * 64)
#define QSCALE 0.18033688011112042f   // (1/8) * log2(e)

#define LQ 72
#define LK 72
#define LV 72
// halves: Q | group g: [K0 V0 K1 V1]
#define H_Q 0
#define H_GK(g, st) (9216 + (g) * 18432 + (st) * 9216)
#define H_GV(g, st) (9216 + (g) * 18432 + (st) * 9216 + 4608)
#define SMEM_BYTES ((9216 + 3 * 18432) * 2)   // 129024

__device__ __half g_kh[NELEM];
__device__ __half g_vh[NELEM];

__device__ __forceinline__ uint32_t smem_u32(const void* p) {
    uint32_t a;
    asm("{ .reg .u64 t; cvta.to.shared.u64 t, %1; cvt.u32.u64 %0, t; }" : "=r"(a) : "l"(p));
    return a;
}
__device__ __forceinline__ uint32_t ex2_h2(uint32_t x) {
    uint32_t y; asm("ex2.approx.f16x2 %0, %1;" : "=r"(y) : "r"(x)); return y;
}
__device__ __forceinline__ void cpa16(uint32_t s, const void* g) {
    asm volatile("cp.async.cg.shared.global [%0], [%1], 16;" :: "r"(s), "l"(g));
}
#define CP_COMMIT() asm volatile("cp.async.commit_group;" ::: "memory")
#define CP_WAIT0()  asm volatile("cp.async.wait_group 0;" ::: "memory")
#define CP_WAIT1()  asm volatile("cp.async.wait_group 1;" ::: "memory")
#define BARG(id)    asm volatile("bar.sync %0, %1;" :: "r"(id), "r"(128) : "memory")

__device__ __forceinline__ void ldsm4(uint32_t& r0, uint32_t& r1, uint32_t& r2,
                                      uint32_t& r3, uint32_t a) {
    asm volatile("ldmatrix.sync.aligned.m8n8.x4.shared.b16 {%0,%1,%2,%3}, [%4];"
                 : "=r"(r0), "=r"(r1), "=r"(r2), "=r"(r3) : "r"(a));
}
__device__ __forceinline__ void ldsm4t(uint32_t& r0, uint32_t& r1, uint32_t& r2,
                                       uint32_t& r3, uint32_t a) {
    asm volatile("ldmatrix.sync.aligned.m8n8.x4.trans.shared.b16 {%0,%1,%2,%3}, [%4];"
                 : "=r"(r0), "=r"(r1), "=r"(r2), "=r"(r3) : "r"(a));
}
__device__ __forceinline__ void ldsm2t(uint32_t& r0, uint32_t& r1, uint32_t a) {
    asm volatile("ldmatrix.sync.aligned.m8n8.x2.trans.shared.b16 {%0,%1}, [%2];"
                 : "=r"(r0), "=r"(r1) : "r"(a));
}
__device__ __forceinline__ void mma16(float d[4], const uint32_t a[4],
                                      uint32_t b0, uint32_t b1) {
    asm volatile(
        "mma.sync.aligned.m16n8k16.row.col.f32.f16.f16.f32 "
        "{%0,%1,%2,%3}, {%4,%5,%6,%7}, {%8,%9}, {%0,%1,%2,%3};"
        : "+f"(d[0]), "+f"(d[1]), "+f"(d[2]), "+f"(d[3])
        : "r"(a[0]), "r"(a[1]), "r"(a[2]), "r"(a[3]), "r"(b0), "r"(b1));
}

// ---- pre-pass: K/V f32 -> f16 ----
__global__ __launch_bounds__(256)
void cvt_f16(const float* __restrict__ k, const float* __restrict__ v) {
    size_t i = ((size_t)blockIdx.x * 256 + threadIdx.x) * 4;
    float4 b = *(const float4*)(k + i);
    *(__half2*)(g_kh + i)     = __floats2half2_rn(b.x, b.y);
    *(__half2*)(g_kh + i + 2) = __floats2half2_rn(b.z, b.w);
    float4 c = *(const float4*)(v + i);
    *(__half2*)(g_vh + i)     = __floats2half2_rn(c.x, c.y);
    *(__half2*)(g_vh + i + 2) = __floats2half2_rn(c.z, c.w);
}

// K+V 64x64 tile into group stage, 128 threads
__device__ __forceinline__ void cp_tile(uint32_t su, uint32_t koh, uint32_t voh,
                                        const __half* kp, const __half* vp, int gtid) {
    #pragma unroll
    for (int i = 0; i < 4; i++) {
        int c = i * 128 + gtid;
        int row = c >> 3, seg = c & 7;
        cpa16(su + (koh + row * LK + seg * 8) * 2, kp + row * 64 + seg * 8);
    }
    #pragma unroll
    for (int i = 0; i < 4; i++) {
        int c = i * 128 + gtid;
        int row = c >> 3, seg = c & 7;
        cpa16(su + (voh + row * LV + seg * 8) * 2, vp + row * 64 + seg * 8);
    }
}

__global__ __launch_bounds__(384, 1)
void fa_f16(const float* __restrict__ qf, float* __restrict__ out) {
    extern __shared__ char smc[];
    const uint32_t su = smem_u32(smc);
    const int tid = threadIdx.x;
    const int g = tid / 128, gtid = tid % 128;
    const int w4 = (tid >> 5) & 3, lane = tid & 31;
    const int lq = lane >> 2, lr = lane & 3;
    const int g8 = lane >> 3, lr8 = lane & 7;
    const int barid = g + 1;

    const int qt = NQT - 1 - (int)blockIdx.x;   // big tiles first
    const int bh = blockIdx.y;
    const int T  = 2 * qt + 2;
    const int ng = (T > g) ? (T - g + 2) / 3 : 0;   // tiles for this group

    const float* qb = qf + ((size_t)bh * S_LEN + (size_t)qt * 128) * 64;
    const __half* kh = g_kh + (size_t)bh * S_LEN * 64;
    const __half* vh = g_vh + (size_t)bh * S_LEN * 64;

    // group prologue: start cp for group's first 1-2 tiles
    if (ng >= 1) cp_tile(su, H_GK(g, 0), H_GV(g, 0),
                         kh + (size_t)g * 4096, vh + (size_t)g * 4096, gtid);
    CP_COMMIT();
    if (ng >= 2) cp_tile(su, H_GK(g, 1), H_GV(g, 1),
                         kh + (size_t)(g + 3) * 4096, vh + (size_t)(g + 3) * 4096, gtid);
    CP_COMMIT();

    // ones columns (col 64 = 1.0, 65-71 = 0) in all 6 V stages (384 threads)
    {
        int sidx = tid >> 6, row = tid & 63;    // 6 stages x 64 rows
        *(uint4*)(smc + (H_GV(sidx >> 1, sidx & 1) + row * LV + 64) * 2) =
            make_uint4(0x00003C00u, 0, 0, 0);
    }
    // Q: f32 LDG -> scaled f16 -> STS (128x64), 2048 float4 slots over 384 thr
    #pragma unroll
    for (int i = 0; i < 6; i++) {
        int c = i * 384 + tid;
        if (c < 2048) {
            int row = c >> 4, seg = c & 15;
            float4 t = *(const float4*)(qb + row * 64 + seg * 4);
            __half2 h0 = __floats2half2_rn(t.x * QSCALE, t.y * QSCALE);
            __half2 h1 = __floats2half2_rn(t.z * QSCALE, t.w * QSCALE);
            uint2 hh = make_uint2(*(uint32_t*)&h0, *(uint32_t*)&h1);
            *(uint2*)(smc + (H_Q + row * LQ + seg * 4) * 2) = hh;
        }
    }
    __syncthreads();   // Q + ones visible

    // hoist Q fragments for both 16-row blocks (invariant): 32 regs
    uint32_t qa[2][4][4];
    #pragma unroll
    for (int b = 0; b < 2; b++)
        #pragma unroll
        for (int ks = 0; ks < 4; ks++) {
            int row = w4 * 32 + b * 16 + (g8 & 1) * 8 + lr8;
            int hc  = ks * 16 + (g8 >> 1) * 8;
            ldsm4(qa[b][ks][0], qa[b][ks][1], qa[b][ks][2], qa[b][ks][3],
                  su + (H_Q + row * LQ + hc) * 2);
        }

    float o[2][9][4];
    #pragma unroll
    for (int b = 0; b < 2; b++)
        #pragma unroll
        for (int n = 0; n < 9; n++)
            #pragma unroll
            for (int e = 0; e < 4; e++) o[b][n][e] = 0.0f;

    const int rg0 = qt * 128 + w4 * 32 + lq;

    if (ng > 0) {
        CP_WAIT1();        // this thread's stage-0 cp done
        BARG(barid);       // whole group sees stage 0

        for (int j = 0; j < ng; j++) {
            const int st = j & 1;
            const int tglob = g + 3 * j;
            const uint32_t koh = H_GK(g, st), voh = H_GV(g, st);
            const bool need_mask = (tglob >= 2 * qt);

            // ---- S = Q @ K^T fused with softmax (np-outer, both blocks) ----
            uint32_t pa[2][4][4];
            #pragma unroll
            for (int np = 0; np < 4; np++) {
                float s00[4] = {0.f,0.f,0.f,0.f}, s01[4] = {0.f,0.f,0.f,0.f};
                float s10[4] = {0.f,0.f,0.f,0.f}, s11[4] = {0.f,0.f,0.f,0.f};
                #pragma unroll
                for (int ks = 0; ks < 4; ks++) {
                    uint32_t b0, b1, b2, b3;
                    int row = (2 * np + (g8 >> 1)) * 8 + lr8;
                    int hc  = ks * 16 + (g8 & 1) * 8;
                    ldsm4(b0, b1, b2, b3, su + (koh + row * LK + hc) * 2);
                    mma16(s00, qa[0][ks], b0, b1);
                    mma16(s01, qa[0][ks], b2, b3);
                    mma16(s10, qa[1][ks], b0, b1);
                    mma16(s11, qa[1][ks], b2, b3);
                }
                if (need_mask) {
                    const int jg0 = tglob * 64 + (2 * np) * 8 + 2 * lr;
                    const int jg1 = jg0 + 8;
                    if (jg0     > rg0     ) s00[0] = -1e30f;
                    if (jg0 + 1 > rg0     ) s00[1] = -1e30f;
                    if (jg0     > rg0 + 8 ) s00[2] = -1e30f;
                    if (jg0 + 1 > rg0 + 8 ) s00[3] = -1e30f;
                    if (jg1     > rg0     ) s01[0] = -1e30f;
                    if (jg1 + 1 > rg0     ) s01[1] = -1e30f;
                    if (jg1     > rg0 + 8 ) s01[2] = -1e30f;
                    if (jg1 + 1 > rg0 + 8 ) s01[3] = -1e30f;
                    if (jg0     > rg0 + 16) s10[0] = -1e30f;
                    if (jg0 + 1 > rg0 + 16) s10[1] = -1e30f;
                    if (jg0     > rg0 + 24) s10[2] = -1e30f;
                    if (jg0 + 1 > rg0 + 24) s10[3] = -1e30f;
                    if (jg1     > rg0 + 16) s11[0] = -1e30f;
                    if (jg1 + 1 > rg0 + 16) s11[1] = -1e30f;
                    if (jg1     > rg0 + 24) s11[2] = -1e30f;
                    if (jg1 + 1 > rg0 + 24) s11[3] = -1e30f;
                }
                __half2 h;
                h = __floats2half2_rn(s00[0], s00[1]); pa[0][np][0] = ex2_h2(*(uint32_t*)&h);
                h = __floats2half2_rn(s00[2], s00[3]); pa[0][np][1] = ex2_h2(*(uint32_t*)&h);
                h = __floats2half2_rn(s01[0], s01[1]); pa[0][np][2] = ex2_h2(*(uint32_t*)&h);
                h = __floats2half2_rn(s01[2], s01[3]); pa[0][np][3] = ex2_h2(*(uint32_t*)&h);
                h = __floats2half2_rn(s10[0], s10[1]); pa[1][np][0] = ex2_h2(*(uint32_t*)&h);
                h = __floats2half2_rn(s10[2], s10[3]); pa[1][np][1] = ex2_h2(*(uint32_t*)&h);
                h = __floats2half2_rn(s11[0], s11[1]); pa[1][np][2] = ex2_h2(*(uint32_t*)&h);
                h = __floats2half2_rn(s11[2], s11[3]); pa[1][np][3] = ex2_h2(*(uint32_t*)&h);
            }

            // ---- O += P @ V  (ones column -> lsum in o[b][8]) ----
            #pragma unroll
            for (int ks = 0; ks < 4; ks++) {
                int row = ks * 16 + (g8 & 1) * 8 + lr8;
                #pragma unroll
                for (int np = 0; np < 4; np++) {
                    uint32_t b0, b1, b2, b3;
                    int hc = (2 * np + (g8 >> 1)) * 8;
                    ldsm4t(b0, b1, b2, b3, su + (voh + row * LV + hc) * 2);
                    mma16(o[0][2 * np],     pa[0][ks], b0, b1);
                    mma16(o[0][2 * np + 1], pa[0][ks], b2, b3);
                    mma16(o[1][2 * np],     pa[1][ks], b0, b1);
                    mma16(o[1][2 * np + 1], pa[1][ks], b2, b3);
                }
                uint32_t w0, w1;
                ldsm2t(w0, w1, su + (voh + row * LV + 64) * 2);
                mma16(o[0][8], pa[0][ks], w0, w1);
                mma16(o[1][8], pa[1][ks], w0, w1);
            }

            BARG(barid);          // group done reading stage st
            if (j + 2 < ng) {
                cp_tile(su, koh, voh, kh + (size_t)(g + 3 * (j + 2)) * 4096,
                                     vh + (size_t)(g + 3 * (j + 2)) * 4096, gtid);
                CP_COMMIT();
                CP_WAIT1();       // group's tile j+1 landed
            } else {
                CP_WAIT0();
            }
            BARG(barid);          // next stage visible to group
        }
    }
    CP_WAIT0();

    // ---- epilogue: groups 1,2 -> smem partials, group 0 merges + stores ----
    __syncthreads();                            // all compute done; smem reusable
    float* smO1 = (float*)smc;                  // 128x64 f32
    float* smL1 = smO1 + 8192;                  // 128 f32
    float* smO2 = smL1 + 128;
    float* smL2 = smO2 + 8192;
    const int r0w = w4 * 32 + lq;
    if (g > 0) {
        float* smO = (g == 1) ? smO1 : smO2;
        float* smL = (g == 1) ? smL1 : smL2;
        #pragma unroll
        for (int b = 0; b < 2; b++) {
            const int rb = r0w + b * 16;
            #pragma unroll
            for (int n = 0; n < 8; n++) {
                const int col = n * 8 + 2 * lr;
                *(float2*)&smO[rb * 64 + col]       = make_float2(o[b][n][0], o[b][n][1]);
                *(float2*)&smO[(rb + 8) * 64 + col] = make_float2(o[b][n][2], o[b][n][3]);
            }
            if (lr == 0) { smL[rb] = o[b][8][0]; smL[rb + 8] = o[b][8][2]; }
        }
    }
    __syncthreads();
    if (g == 0) {
        #pragma unroll
        for (int b = 0; b < 2; b++) {
            const int rb = r0w + b * 16;
            float l0 = __shfl_sync(0xffffffffu, o[b][8][0], lane & ~3)
                     + smL1[rb] + smL2[rb];
            float l1 = __shfl_sync(0xffffffffu, o[b][8][2], lane & ~3)
                     + smL1[rb + 8] + smL2[rb + 8];
            const float inv0 = __fdividef(1.0f, l0);
            const float inv1 = __fdividef(1.0f, l1);
            float* ob = out + ((size_t)bh * S_LEN + qt * 128 + rb) * 64;
            #pragma unroll
            for (int n = 0; n < 8; n++) {
                const int col = n * 8 + 2 * lr;
                float2 p0 = *(float2*)&smO1[rb * 64 + col];
                float2 q0 = *(float2*)&smO2[rb * 64 + col];
                float2 p1 = *(float2*)&smO1[(rb + 8) * 64 + col];
                float2 q1 = *(float2*)&smO2[(rb + 8) * 64 + col];
                *(float2*)(ob + col) =
                    make_float2((o[b][n][0] + p0.x + q0.x) * inv0,
                                (o[b][n][1] + p0.y + q0.y) * inv0);
                *(float2*)(ob + 8 * 64 + col) =
                    make_float2((o[b][n][2] + p1.x + q1.x) * inv1,
                                (o[b][n][3] + p1.y + q1.y) * inv1);
            }
        }
    }
}

extern "C" void kernel_launch(void* const* d_in, const int* in_sizes, int n_in,
                              void* d_out, int out_size) {
    (void)in_sizes; (void)n_in; (void)out_size;
    cvt_f16<<<NELEM / (256 * 4), 256>>>((const float*)d_in[1], (const float*)d_in[2]);
    cudaFuncSetAttribute(fa_f16, cudaFuncAttributeMaxDynamicSharedMemorySize, SMEM_BYTES);
    dim3 grid(NQT, NBH);
    fa_f16<<<grid, 384, SMEM_BYTES>>>((const float*)d_in[0], (float*)d_out);
}

// round 14
// speedup vs baseline: 1.4980x; 1.0940x over previous
#include <cuda_runtime.h>
#include <cuda_fp16.h>
#include <cstdint>

#define S_LEN 2048
#define NQT 16
#define NBH 32
#define NELEM (NBH * S_LEN * 64)
#define QSCALE 0.18033688011112042f   // (1/8) * log2(e)

#define LQ 72
#define LK 72
#define LV 72
// half-unit offsets: Q | g0:K0 K1 V0 V1 | g1:K0 K1 V0 V1
#define H_Q    0
#define H_GK(g, st) (9216 + (g) * 18432 + (st) * 4608)
#define H_GV(g, st) (18432 + (g) * 18432 + (st) * 4608)
#define SMEM_BYTES (46080 * 2)   // 92160

__device__ __half g_kh[NELEM];
__device__ __half g_vh[NELEM];

__device__ __forceinline__ uint32_t smem_u32(const void* p) {
    uint32_t a;
    asm("{ .reg .u64 t; cvta.to.shared.u64 t, %1; cvt.u32.u64 %0, t; }" : "=r"(a) : "l"(p));
    return a;
}
__device__ __forceinline__ uint32_t ex2_h2(uint32_t x) {
    uint32_t y; asm("ex2.approx.f16x2 %0, %1;" : "=r"(y) : "r"(x)); return y;
}
__device__ __forceinline__ void cpa16(uint32_t s, const void* g) {
    asm volatile("cp.async.cg.shared.global [%0], [%1], 16;" :: "r"(s), "l"(g));
}
#define CP_COMMIT() asm volatile("cp.async.commit_group;" ::: "memory")
#define CP_WAIT0()  asm volatile("cp.async.wait_group 0;" ::: "memory")
#define CP_WAIT1()  asm volatile("cp.async.wait_group 1;" ::: "memory")
#define BARG(id)    asm volatile("bar.sync %0, %1;" :: "r"(id), "r"(256) : "memory")

__device__ __forceinline__ void ldsm4(uint32_t& r0, uint32_t& r1, uint32_t& r2,
                                      uint32_t& r3, uint32_t a) {
    asm volatile("ldmatrix.sync.aligned.m8n8.x4.shared.b16 {%0,%1,%2,%3}, [%4];"
                 : "=r"(r0), "=r"(r1), "=r"(r2), "=r"(r3) : "r"(a));
}
__device__ __forceinline__ void ldsm4t(uint32_t& r0, uint32_t& r1, uint32_t& r2,
                                       uint32_t& r3, uint32_t a) {
    asm volatile("ldmatrix.sync.aligned.m8n8.x4.trans.shared.b16 {%0,%1,%2,%3}, [%4];"
                 : "=r"(r0), "=r"(r1), "=r"(r2), "=r"(r3) : "r"(a));
}
__device__ __forceinline__ void ldsm2t(uint32_t& r0, uint32_t& r1, uint32_t a) {
    asm volatile("ldmatrix.sync.aligned.m8n8.x2.trans.shared.b16 {%0,%1}, [%2];"
                 : "=r"(r0), "=r"(r1) : "r"(a));
}
__device__ __forceinline__ void mma16(float d[4], const uint32_t a[4],
                                      uint32_t b0, uint32_t b1) {
    asm volatile(
        "mma.sync.aligned.m16n8k16.row.col.f32.f16.f16.f32 "
        "{%0,%1,%2,%3}, {%4,%5,%6,%7}, {%8,%9}, {%0,%1,%2,%3};"
        : "+f"(d[0]), "+f"(d[1]), "+f"(d[2]), "+f"(d[3])
        : "r"(a[0]), "r"(a[1]), "r"(a[2]), "r"(a[3]), "r"(b0), "r"(b1));
}

// ---- pre-pass: K/V f32 -> f16 ----
__global__ __launch_bounds__(256)
void cvt_f16(const float* __restrict__ k, const float* __restrict__ v) {
    size_t i = ((size_t)blockIdx.x * 256 + threadIdx.x) * 4;
    float4 b = *(const float4*)(k + i);
    *(__half2*)(g_kh + i)     = __floats2half2_rn(b.x, b.y);
    *(__half2*)(g_kh + i + 2) = __floats2half2_rn(b.z, b.w);
    float4 c = *(const float4*)(v + i);
    *(__half2*)(g_vh + i)     = __floats2half2_rn(c.x, c.y);
    *(__half2*)(g_vh + i + 2) = __floats2half2_rn(c.z, c.w);
}

// group tile load: 64x64 halves, 256 threads
__device__ __forceinline__ void cp_tile(uint32_t su, uint32_t off_h,
                                        const __half* g, int gtid) {
    #pragma unroll
    for (int i = 0; i < 2; i++) {
        int c = i * 256 + gtid;
        int row = c >> 3, seg = c & 7;
        cpa16(su + (off_h + row * LK + seg * 8) * 2, g + row * 64 + seg * 8);
    }
}

__global__ __launch_bounds__(512, 1)
void fa_f16(const float* __restrict__ qf, float* __restrict__ out) {
    extern __shared__ char smc[];
    const uint32_t su = smem_u32(smc);
    const int tid = threadIdx.x;
    const int g = tid >> 8, gtid = tid & 255;
    const int w8 = (tid >> 5) & 7, lane = tid & 31;
    const int lq = lane >> 2, lr = lane & 3;
    const int g8 = lane >> 3, lr8 = lane & 7;
    const int barid = g + 1;

    const int qt = NQT - 1 - (int)blockIdx.x;   // big tiles first
    const int bh = blockIdx.y;

    const float* qb = qf + ((size_t)bh * S_LEN + (size_t)qt * 128) * 64;
    const __half* kh = g_kh + (size_t)bh * S_LEN * 64;
    const __half* vh = g_vh + (size_t)bh * S_LEN * 64;

    // ones columns (col 64 = 1.0) in all 4 V stages
    if (tid < 256) {
        int vbuf = tid >> 6, row = tid & 63;
        uint32_t voh = H_GV(vbuf >> 1, vbuf & 1);
        *(uint4*)(smc + (voh + row * LV + 64) * 2) = make_uint4(0x00003C00u, 0, 0, 0);
    }
    // Q: f32 LDG -> scaled f16 -> STS (128x64)
    #pragma unroll
    for (int i = 0; i < 4; i++) {
        int c = i * 512 + tid;                     // 2048 float4(f32) slots
        int row = c >> 4, seg = c & 15;
        float4 t = *(const float4*)(qb + row * 64 + seg * 4);
        __half2 h0 = __floats2half2_rn(t.x * QSCALE, t.y * QSCALE);
        __half2 h1 = __floats2half2_rn(t.z * QSCALE, t.w * QSCALE);
        uint2 hh = make_uint2(*(uint32_t*)&h0, *(uint32_t*)&h1);
        *(uint2*)(smc + (H_Q + row * LQ + seg * 4) * 2) = hh;
    }
    // group prologue: global tile t = 2*it + g
    cp_tile(su, H_GK(g, 0), kh + (size_t)(0 + g) * 4096, gtid);
    cp_tile(su, H_GV(g, 0), vh + (size_t)(0 + g) * 4096, gtid);
    CP_COMMIT();
    if (qt >= 1) {
        cp_tile(su, H_GK(g, 1), kh + (size_t)(2 + g) * 4096, gtid);
        cp_tile(su, H_GV(g, 1), vh + (size_t)(2 + g) * 4096, gtid);
        CP_COMMIT();
        CP_WAIT1();
    } else {
        CP_WAIT0();
    }
    __syncthreads();   // Q + ones + stage0 visible to all

    // hoist Q fragments (invariant across k-tiles): 16 regs
    uint32_t qa[4][4];
    #pragma unroll
    for (int ks = 0; ks < 4; ks++) {
        int row = w8 * 16 + (g8 & 1) * 8 + lr8;
        int hc  = ks * 16 + (g8 >> 1) * 8;
        ldsm4(qa[ks][0], qa[ks][1], qa[ks][2], qa[ks][3],
              su + (H_Q + row * LQ + hc) * 2);
    }

    float o[9][4];
    #pragma unroll
    for (int n = 0; n < 9; n++)
        #pragma unroll
        for (int e = 0; e < 4; e++) o[n][e] = 0.0f;

    const int rg0 = qt * 128 + w8 * 16 + lq;

    for (int it = 0; it <= qt; it++) {
        const int st = it & 1;
        const uint32_t koh = H_GK(g, st), voh = H_GV(g, st);
        const bool need_mask = (it == qt);
        const int tglob = 2 * it + g;

        // ---- fully interleaved: per 16-col chunk np:
        //      S(np) -> softmax(np) -> PV(np)  (PV chunk ks == np) ----
        #pragma unroll
        for (int np = 0; np < 4; np++) {
            // S chunk: columns 16np .. 16np+15
            float s0[4] = {0.f, 0.f, 0.f, 0.f};
            float s1[4] = {0.f, 0.f, 0.f, 0.f};
            #pragma unroll
            for (int ks = 0; ks < 4; ks++) {
                uint32_t b0, b1, b2, b3;
                int row = (2 * np + (g8 >> 1)) * 8 + lr8;
                int hc  = ks * 16 + (g8 & 1) * 8;
                ldsm4(b0, b1, b2, b3, su + (koh + row * LK + hc) * 2);
                mma16(s0, qa[ks], b0, b1);
                mma16(s1, qa[ks], b2, b3);
            }
            // softmax for this chunk
            if (need_mask) {
                const int jg0 = tglob * 64 + (2 * np) * 8 + 2 * lr;
                if (jg0     > rg0    ) s0[0] = -1e30f;
                if (jg0 + 1 > rg0    ) s0[1] = -1e30f;
                if (jg0     > rg0 + 8) s0[2] = -1e30f;
                if (jg0 + 1 > rg0 + 8) s0[3] = -1e30f;
                const int jg1 = jg0 + 8;
                if (jg1     > rg0    ) s1[0] = -1e30f;
                if (jg1 + 1 > rg0    ) s1[1] = -1e30f;
                if (jg1     > rg0 + 8) s1[2] = -1e30f;
                if (jg1 + 1 > rg0 + 8) s1[3] = -1e30f;
            }
            uint32_t pc[4];
            __half2 a01 = __floats2half2_rn(s0[0], s0[1]);   // masked -> -inf
            __half2 a23 = __floats2half2_rn(s0[2], s0[3]);
            __half2 b01 = __floats2half2_rn(s1[0], s1[1]);
            __half2 b23 = __floats2half2_rn(s1[2], s1[3]);
            pc[0] = ex2_h2(*(uint32_t*)&a01);                // ex2(-inf) = 0
            pc[1] = ex2_h2(*(uint32_t*)&a23);
            pc[2] = ex2_h2(*(uint32_t*)&b01);
            pc[3] = ex2_h2(*(uint32_t*)&b23);

            // PV chunk: V rows 16np .. 16np+15 (k-slice matching this P chunk)
            int vrow = np * 16 + (g8 & 1) * 8 + lr8;
            #pragma unroll
            for (int vn = 0; vn < 4; vn++) {
                uint32_t b0, b1, b2, b3;
                int hc = (2 * vn + (g8 >> 1)) * 8;
                ldsm4t(b0, b1, b2, b3, su + (voh + vrow * LV + hc) * 2);
                mma16(o[2 * vn],     pc, b0, b1);
                mma16(o[2 * vn + 1], pc, b2, b3);
            }
            uint32_t w0, w1;
            ldsm2t(w0, w1, su + (voh + vrow * LV + 64) * 2);
            mma16(o[8], pc, w0, w1);                         // ones -> lsum
        }

        BARG(barid);              // group done reading stage st
        if (it + 2 <= qt) {
            cp_tile(su, koh, kh + (size_t)(2 * (it + 2) + g) * 4096, gtid);
            cp_tile(su, voh, vh + (size_t)(2 * (it + 2) + g) * 4096, gtid);
            CP_COMMIT();
            CP_WAIT1();
        } else {
            CP_WAIT0();
        }
        BARG(barid);              // next stage visible to group
    }

    // ---- epilogue: group1 -> smem partials, group0 combines + stores ----
    float* smO = (float*)(smc + H_GK(1, 0) * 2);   // group1 K/V area (dead now)
    float* smL = smO + 128 * 64;
    const int r0b = w8 * 16 + lq;
    if (g == 1) {
        #pragma unroll
        for (int n = 0; n < 8; n++) {
            const int col = n * 8 + 2 * lr;
            *(float2*)&smO[r0b * 64 + col]       = make_float2(o[n][0], o[n][1]);
            *(float2*)&smO[(r0b + 8) * 64 + col] = make_float2(o[n][2], o[n][3]);
        }
        if (lr == 0) { smL[r0b] = o[8][0]; smL[r0b + 8] = o[8][2]; }
    }
    __syncthreads();
    if (g == 0) {
        float l0 = __shfl_sync(0xffffffffu, o[8][0], lane & ~3) + smL[r0b];
        float l1 = __shfl_sync(0xffffffffu, o[8][2], lane & ~3) + smL[r0b + 8];
        const float inv0 = __fdividef(1.0f, l0);
        const float inv1 = __fdividef(1.0f, l1);
        float* ob = out + ((size_t)bh * S_LEN + qt * 128 + r0b) * 64;
        #pragma unroll
        for (int n = 0; n < 8; n++) {
            const int col = n * 8 + 2 * lr;
            float2 p0 = *(float2*)&smO[r0b * 64 + col];
            float2 p1 = *(float2*)&smO[(r0b + 8) * 64 + col];
            *(float2*)(ob + col) =
                make_float2((o[n][0] + p0.x) * inv0, (o[n][1] + p0.y) * inv0);
            *(float2*)(ob + 8 * 64 + col) =
                make_float2((o[n][2] + p1.x) * inv1, (o[n][3] + p1.y) * inv1);
        }
    }
}

extern "C" void kernel_launch(void* const* d_in, const int* in_sizes, int n_in,
                              void* d_out, int out_size) {
    (void)in_sizes; (void)n_in; (void)out_size;
    cvt_f16<<<NELEM / (256 * 4), 256>>>((const float*)d_in[1], (const float*)d_in[2]);
    cudaFuncSetAttribute(fa_f16, cudaFuncAttributeMaxDynamicSharedMemorySize, SMEM_BYTES);
    dim3 grid(NQT, NBH);
    fa_f16<<<grid, 512, SMEM_BYTES>>>((const float*)d_in[0], (float*)d_out);
}